// round 17
// baseline (speedup 1.0000x reference)
#include <cuda_runtime.h>
#include <cuda_fp16.h>
#include <math.h>
#include <stdint.h>

#define Bq 32
#define Vq 2048
#define Pq 64
#define Aq 8
#define Fq 72          // P + A
#define NFq 128
#define TWOF 144       // 2*F
#define NPC 64         // partial slots per batch (= 16 chunks * 4 subsets)

// Scratch (device globals; no allocation allowed)
__device__ __half g_Xh  [Bq * Vq * Pq];                // X fp16 (produced by k1)
__device__ __half g_aggH [Bq * Vq * Aq];               // agg fp16
__device__ __half g_MTh  [Bq * NFq * Aq];              // M transposed fp16
__device__ __half g_WoutH[NFq * 64];                   // [n][k] fp16 Wout_top^T
__device__ float  g_pmax [Bq * NPC * Aq * Fq];
__device__ float  g_psum [Bq * NPC * Aq * Fq];

__device__ __forceinline__ void mma_f16(float* d, const uint32_t* a, const uint32_t* b) {
    asm("mma.sync.aligned.m16n8k16.row.col.f32.f16.f16.f32 "
        "{%0,%1,%2,%3},{%4,%5,%6,%7},{%8,%9},{%0,%1,%2,%3};"
        : "+f"(d[0]), "+f"(d[1]), "+f"(d[2]), "+f"(d[3])
        : "r"(a[0]), "r"(a[1]), "r"(a[2]), "r"(a[3]), "r"(b[0]), "r"(b[1]));
}
__device__ __forceinline__ uint32_t s2u(const void* p) {
    return (uint32_t)__cvta_generic_to_shared(p);
}
__device__ __forceinline__ void ldsm4(uint32_t* r, uint32_t addr) {
    asm volatile("ldmatrix.sync.aligned.m8n8.x4.shared.b16 {%0,%1,%2,%3}, [%4];"
                 : "=r"(r[0]), "=r"(r[1]), "=r"(r[2]), "=r"(r[3]) : "r"(addr));
}
__device__ __forceinline__ void ldsm2(uint32_t* r, uint32_t addr) {
    asm volatile("ldmatrix.sync.aligned.m8n8.x2.shared.b16 {%0,%1}, [%2];"
                 : "=r"(r[0]), "=r"(r[1]) : "r"(addr));
}
__device__ __forceinline__ uint32_t pack_h2(float a, float b) {
    __half2 h = __floats2half2_rn(a, b);
    return *(uint32_t*)&h;
}
__device__ __forceinline__ float ftanh(float x) {
    float e = __expf(2.0f * x);
    return 1.0f - __fdividef(2.0f, e + 1.0f);
}
__device__ __forceinline__ void cpasync16(uint32_t dst, const void* src) {
    asm volatile("cp.async.cg.shared.global [%0], [%1], 16;" :: "r"(dst), "l"(src));
}

// ---------------------------------------------------------------------------
// k1: grid 256, 2 tiles (128 rows) per CTA. Raw fp32 X double-buffered via
// cp.async; per-tile convert pass -> fp16 A tile (also exported to g_Xh for
// k3); fp16 m16n8k16 MMA (4 ksteps). Wt self-staged. Tail: g_WoutH.
// 576 threads = 18 warps. MMA: warps 0-15 (8 rg x 2 ng). Reduce: 4 subsets.
// ---------------------------------------------------------------------------
#define XS1 68         // raw X float stride
#define SFS 80         // float stride of feats tile
#define BUF1 10240     // words per raw/sf buffer (128*80)
#define XH1 72         // fp16 A tile half-stride (144 B)
#define WS1 72         // fp16 Wt half-stride (144 B)
__global__ void __launch_bounds__(576, 2)
k1(const float* __restrict__ X,
   const float* __restrict__ W1, const float* __restrict__ b1,
   const float* __restrict__ W2, const float* __restrict__ b2,
   const float* __restrict__ Wout) {
    extern __shared__ uint32_t smu[];
    __half* Xh  = (__half*)(smu + 2 * BUF1);          // [128][72] halves
    __half* Wt1 = Xh + 128 * XH1;                     // [72][72] halves
    float*  bs  = (float*)(Wt1 + Fq * WS1);           // [72]

    const int tid = threadIdx.x;
    const int bid = blockIdx.x;
    const int wid = tid >> 5, lane = tid & 31;
    const int lq = lane & 3, lg = lane >> 2;
    const int rA = lane & 15;
    const int cA = (lane & 16) >> 1;                  // halves
    const int rB = (lane & 7) + ((lane & 16) >> 1);
    const int cB = (lane & 8);                        // halves

    // prologue: X raw copies first (fly during the W staging below)
    {
        const float* src = X + (long)(bid * 2) * 128 * Pq;
        for (int i = tid; i < 128 * 16; i += 576) {
            int r = i >> 4, c = i & 15;
            cpasync16(s2u(smu + r * XS1 + c * 4), src + r * Pq + c * 4);
        }
    }
    asm volatile("cp.async.commit_group;");
    {
        const float* src = X + (long)(bid * 2 + 1) * 128 * Pq;
        for (int i = tid; i < 128 * 16; i += 576) {
            int r = i >> 4, c = i & 15;
            cpasync16(s2u(smu + BUF1 + r * XS1 + c * 4), src + r * Pq + c * 4);
        }
    }
    asm volatile("cp.async.commit_group;");

    // Wt self-stage: coalesced LDG, cvt fp16, transposed STS
    {
        float v1[8];
#pragma unroll
        for (int t = 0; t < 8; t++) {
            int i = tid + t * 576;
            v1[t] = (i < 64 * 64) ? W1[i] : 0.f;
        }
        float v2 = (tid < 64 * Aq) ? W2[tid] : 0.f;
#pragma unroll
        for (int t = 0; t < 8; t++) {
            int i = tid + t * 576;
            if (i < 64 * 64) {
                int k = i >> 6, n = i & 63;
                Wt1[n * WS1 + k] = __float2half_rn(v1[t]);
            }
        }
        if (tid < 64 * Aq) {
            int k = tid >> 3, n = tid & 7;
            Wt1[(64 + n) * WS1 + k] = __float2half_rn(v2);
        }
    }
    if (tid < Fq) bs[tid] = (tid < Pq) ? b1[tid] : b2[tid - Pq];

#pragma unroll
    for (int j = 0; j < 2; j++) {
        const int tile = bid * 2 + j;
        const long row0 = (long)tile * 128;
        const int b = tile >> 4, chunk = tile & 15;
        uint32_t* xb = smu + j * BUF1;
        float*    sf = (float*)xb;

        if (j == 0) asm volatile("cp.async.wait_group 1;");
        else        asm volatile("cp.async.wait_group 0;");
        __syncthreads();

        // convert raw fp32 -> fp16 A tile (also export to g_Xh for k3)
        for (int i = tid; i < 128 * 16; i += 576) {
            int r = i >> 4, c = i & 15;
            float4 v = *(const float4*)((const float*)xb + r * XS1 + c * 4);
            uint2 h = make_uint2(pack_h2(v.x, v.y), pack_h2(v.z, v.w));
            *(uint2*)(Xh + r * XH1 + c * 4) = h;
            *(uint2*)(g_Xh + (row0 + r) * Pq + c * 4) = h;
        }
        __syncthreads();

        float d[5][4];
        const int rg = wid & 7, wg = wid >> 3;
        if (wid < 16) {
            uint32_t aAddr = s2u(Xh + (rg * 16 + rA) * XH1 + cA);
#pragma unroll
            for (int nt = 0; nt < 5; nt++)
#pragma unroll
                for (int r = 0; r < 4; r++) d[nt][r] = 0.f;

            if (wg == 0) {
                uint32_t b0  = s2u(Wt1 + (0  + rB) * WS1 + cB);
                uint32_t b1a = s2u(Wt1 + (16 + rB) * WS1 + cB);
                uint32_t b2a = s2u(Wt1 + (32 + (lane & 7)) * WS1 + cB);
#pragma unroll
                for (int ks = 0; ks < 4; ks++) {
                    uint32_t a[4];
                    ldsm4(a, aAddr); aAddr += 32;
                    uint32_t bf[5][2];
                    ldsm4(&bf[0][0], b0);  b0  += 32;
                    ldsm4(&bf[2][0], b1a); b1a += 32;
                    ldsm2(bf[4], b2a);     b2a += 32;
#pragma unroll
                    for (int nt = 0; nt < 5; nt++) mma_f16(d[nt], a, bf[nt]);
                }
            } else {
                uint32_t b0  = s2u(Wt1 + (40 + rB) * WS1 + cB);
                uint32_t b1a = s2u(Wt1 + (56 + rB) * WS1 + cB);
#pragma unroll
                for (int ks = 0; ks < 4; ks++) {
                    uint32_t a[4];
                    ldsm4(a, aAddr); aAddr += 32;
                    uint32_t bf[4][2];
                    ldsm4(&bf[0][0], b0);  b0  += 32;
                    ldsm4(&bf[2][0], b1a); b1a += 32;
#pragma unroll
                    for (int nt = 0; nt < 4; nt++) mma_f16(d[nt], a, bf[nt]);
                }
            }
        }
        __syncthreads();   // raw X + Xh reads done; safe to overwrite xb with sf

        if (wid < 16) {
            const int orow = rg * 16 + lg;
            if (wg == 0) {
#pragma unroll
                for (int nt = 0; nt < 5; nt++) {
                    const int col = nt * 8 + 2 * lq;
                    *(float2*)&sf[orow * SFS + col] =
                        make_float2(d[nt][0] + bs[col], d[nt][1] + bs[col + 1]);
                    *(float2*)&sf[(orow + 8) * SFS + col] =
                        make_float2(d[nt][2] + bs[col], d[nt][3] + bs[col + 1]);
                }
            } else {
#pragma unroll
                for (int nt = 0; nt < 3; nt++) {
                    const int col = (nt + 5) * 8 + 2 * lq;
                    *(float2*)&sf[orow * SFS + col] =
                        make_float2(d[nt][0] + bs[col], d[nt][1] + bs[col + 1]);
                    *(float2*)&sf[(orow + 8) * SFS + col] =
                        make_float2(d[nt][2] + bs[col], d[nt][3] + bs[col + 1]);
                }
                {   // agg cols 64..71
                    const int col = 64 + 2 * lq;
                    float e0 = __expf(-fabsf(d[3][0] + bs[col]));
                    float e1 = __expf(-fabsf(d[3][1] + bs[col + 1]));
                    float e2 = __expf(-fabsf(d[3][2] + bs[col]));
                    float e3 = __expf(-fabsf(d[3][3] + bs[col + 1]));
                    *(float2*)&sf[orow * SFS + col]       = make_float2(e0, e1);
                    *(float2*)&sf[(orow + 8) * SFS + col] = make_float2(e2, e3);
                    *(uint32_t*)(g_aggH + (row0 + orow) * Aq + 2 * lq)     = pack_h2(e0, e1);
                    *(uint32_t*)(g_aggH + (row0 + orow + 8) * Aq + 2 * lq) = pack_h2(e2, e3);
                }
            }
        }
        __syncthreads();

        // partial reduce: 4 subsets of 32 v; thread -> (a, f4 quad)
        {
            const int sub = tid / 144;
            const int t   = tid % 144;
            const int a8  = t & 7;
            const int f4  = t >> 3;
            const int vbase = sub * 32;

            float4 mx = make_float4(-INFINITY, -INFINITY, -INFINITY, -INFINITY);
            float4 sv = make_float4(0.f, 0.f, 0.f, 0.f);
#pragma unroll 8
            for (int i = 0; i < 32; i++) {
                const int v = vbase + i;
                float e = sf[v * SFS + 64 + a8];
                float4 x = *(float4*)&sf[v * SFS + f4 * 4];
                float p0 = e * x.x, p1 = e * x.y, p2 = e * x.z, p3 = e * x.w;
                mx.x = fmaxf(mx.x, p0); mx.y = fmaxf(mx.y, p1);
                mx.z = fmaxf(mx.z, p2); mx.w = fmaxf(mx.w, p3);
                sv.x += p0; sv.y += p1; sv.z += p2; sv.w += p3;
            }
            const int pc = chunk * 4 + sub;
            const long o = (((long)b * NPC + pc) * Aq + a8) * Fq + f4 * 4;
            *(float4*)(g_pmax + o) = mx;
            *(float4*)(g_psum + o) = sv;
        }
        __syncthreads();
    }

    // tail: CTAs 0-7 produce g_WoutH (n-major fp16 of Wout top 64 rows)
    if (bid < 8) {
        const int n0 = bid * 16;
        for (int i = tid; i < 64 * 16; i += 576) {
            int k = i >> 4, j = i & 15;
            g_WoutH[(n0 + j) * 64 + k] = __float2half_rn(Wout[k * NFq + n0 + j]);
        }
    }
}

// ---------------------------------------------------------------------------
// kB2: combine partials -> collapsed[a,2F]; MTh[b,n,a] fp16
// ---------------------------------------------------------------------------
__global__ void __launch_bounds__(576)
kB2(const float* __restrict__ Wout) {
    const int b = blockIdx.x;
    const int tid = threadIdx.x;
    const int a = tid % Aq;
    const int f = tid / Aq;

    __shared__ float scol[Aq][TWOF];

    {
        float vmax = -INFINITY, vsum = 0.f;
        const long base = ((long)b * NPC) * Aq * Fq + a * Fq + f;
#pragma unroll 8
        for (int pc = 0; pc < NPC; pc++) {
            vmax = fmaxf(vmax, g_pmax[base + (long)pc * Aq * Fq]);
            vsum += g_psum[base + (long)pc * Aq * Fq];
        }
        scol[a][f]      = vmax;
        scol[a][Fq + f] = vsum * (1.0f / (float)Vq);
    }
    __syncthreads();

    for (int idx = tid; idx < Aq * NFq; idx += 576) {
        int aa = idx / NFq, n = idx % NFq;
        float acc = Wout[(Pq + Aq * TWOF + aa) * NFq + n];
#pragma unroll 16
        for (int g = 0; g < TWOF; g++) {
            acc = fmaf(scol[aa][g], Wout[(Pq + aa * TWOF + g) * NFq + n], acc);
        }
        g_MTh[((long)b * NFq + n) * Aq + aa] = __float2half_rn(acc);
    }
}

// ---------------------------------------------------------------------------
// k3: grid 256, 2 tiles (128 rows) per CTA, b constant per CTA. fp16
// m16n8k16 MMA, K padded 72->80 (5 ksteps). X already fp16 (g_Xh): straight
// cp.async into double-buffered A tiles, no convert pass, 1 barrier/tile.
// 512 threads = 16 warps (4m x 4n).
// ---------------------------------------------------------------------------
#define XM3 88         // fp16 A tile half-stride (176 B)
#define WS3 88         // fp16 Wt half-stride (176 B)
__global__ void __launch_bounds__(512, 2)
k3(const float* __restrict__ bout, float* __restrict__ out) {
    extern __shared__ uint32_t sm3[];
    __half* Xm0 = (__half*)sm3;                       // [128][88] halves
    __half* Xm1 = Xm0 + 128 * XM3;
    __half* WtH = Xm1 + 128 * XM3;                    // [128][88] halves
    float*  bC  = (float*)(WtH + 128 * WS3);          // [128]

    const int tid = threadIdx.x;
    const int bid = blockIdx.x;
    const int b   = bid >> 3;
    const int wid = tid >> 5, lane = tid & 31;
    const int wm = (wid >> 2) & 3, wn = wid & 3;
    const int lq = lane & 3, lg = lane >> 2;
    const int rA = lane & 15;
    const int cA = (lane & 16) >> 1;                  // halves
    const int rB = (lane & 7) + ((lane & 16) >> 1);
    const int cB = (lane & 8);                        // halves

    const long row0 = (long)(bid * 2) * 128;

    // group 0: Wt (WoutH + MTh) + tile-0 X/agg
    for (int i = tid; i < NFq * 8; i += 512) {
        int n = i >> 3, c = i & 7;
        cpasync16(s2u(WtH + n * WS3 + c * 8), g_WoutH + n * 64 + c * 8);
    }
    for (int i = tid; i < NFq; i += 512) {
        cpasync16(s2u(WtH + i * WS3 + 64), g_MTh + ((long)b * NFq + i) * Aq);
    }
    for (int i = tid; i < 128 * 8; i += 512) {
        int r = i >> 3, c = i & 7;
        cpasync16(s2u(Xm0 + r * XM3 + c * 8), g_Xh + (row0 + r) * Pq + c * 8);
    }
    for (int r = tid; r < 128; r += 512) {
        cpasync16(s2u(Xm0 + r * XM3 + 64), g_aggH + (row0 + r) * Aq);
    }
    asm volatile("cp.async.commit_group;");
    // group 1: tile-1 X/agg
    for (int i = tid; i < 128 * 8; i += 512) {
        int r = i >> 3, c = i & 7;
        cpasync16(s2u(Xm1 + r * XM3 + c * 8), g_Xh + (row0 + 128 + r) * Pq + c * 8);
    }
    for (int r = tid; r < 128; r += 512) {
        cpasync16(s2u(Xm1 + r * XM3 + 64), g_aggH + (row0 + 128 + r) * Aq);
    }
    asm volatile("cp.async.commit_group;");

    // zero pads (k 72..79) for both A tiles and Wt (published by first sync)
    {
        uint4 z = make_uint4(0, 0, 0, 0);
        for (int r = tid; r < 128; r += 512) {
            *(uint4*)(Xm0 + r * XM3 + 72) = z;
            *(uint4*)(Xm1 + r * XM3 + 72) = z;
            *(uint4*)(WtH + r * WS3 + 72) = z;
        }
    }
    if (tid < NFq) bC[tid] = bout[tid];

#pragma unroll
    for (int j = 0; j < 2; j++) {
        const long trow0 = row0 + (long)j * 128;
        __half* Xm = (j == 0) ? Xm0 : Xm1;

        if (j == 0) asm volatile("cp.async.wait_group 1;");
        else        asm volatile("cp.async.wait_group 0;");
        __syncthreads();

        uint32_t aAddr[2], bAddr[2];
#pragma unroll
        for (int mt = 0; mt < 2; mt++)
            aAddr[mt] = s2u(Xm + (wm * 32 + mt * 16 + rA) * XM3 + cA);
#pragma unroll
        for (int p = 0; p < 2; p++)
            bAddr[p] = s2u(WtH + (wn * 32 + p * 16 + rB) * WS3 + cB);

        float d[2][4][4];
#pragma unroll
        for (int mt = 0; mt < 2; mt++)
#pragma unroll
            for (int nt = 0; nt < 4; nt++)
#pragma unroll
                for (int r = 0; r < 4; r++) d[mt][nt][r] = 0.f;

#pragma unroll
        for (int ks = 0; ks < 5; ks++) {
            uint32_t a[2][4];
#pragma unroll
            for (int mt = 0; mt < 2; mt++) {
                ldsm4(a[mt], aAddr[mt]); aAddr[mt] += 32;
            }
            uint32_t bf[4][2];
#pragma unroll
            for (int p = 0; p < 2; p++) {
                ldsm4(&bf[2 * p][0], bAddr[p]); bAddr[p] += 32;
            }
#pragma unroll
            for (int mt = 0; mt < 2; mt++)
#pragma unroll
                for (int nt = 0; nt < 4; nt++)
                    mma_f16(d[mt][nt], a[mt], bf[nt]);
        }

#pragma unroll
        for (int mt = 0; mt < 2; mt++) {
            const long r0 = trow0 + wm * 32 + mt * 16 + lg;
#pragma unroll
            for (int nt = 0; nt < 4; nt++) {
                const int c0 = wn * 32 + nt * 8 + 2 * lq;
                float2 o0, o1;
                o0.x = ftanh(d[mt][nt][0] + bC[c0]);
                o0.y = ftanh(d[mt][nt][1] + bC[c0 + 1]);
                o1.x = ftanh(d[mt][nt][2] + bC[c0]);
                o1.y = ftanh(d[mt][nt][3] + bC[c0 + 1]);
                *(float2*)(out + (r0)     * NFq + c0) = o0;
                *(float2*)(out + (r0 + 8) * NFq + c0) = o1;
            }
        }
    }
}

// ---------------------------------------------------------------------------
extern "C" void kernel_launch(void* const* d_in, const int* in_sizes, int n_in,
                              void* d_out, int out_size) {
    const float* X    = (const float*)d_in[0];
    const float* W1   = (const float*)d_in[1];
    const float* b1   = (const float*)d_in[2];
    const float* W2   = (const float*)d_in[3];
    const float* b2   = (const float*)d_in[4];
    const float* Wout = (const float*)d_in[5];
    const float* bout = (const float*)d_in[6];
    float* out = (float*)d_out;

    const int smem1 = 2 * BUF1 * 4 + 128 * XH1 * 2 + Fq * WS1 * 2 + Fq * 4;       // ~108.4 KB
    const int smem3 = (2 * 128 * XM3 + 128 * WS3) * 2 + NFq * 4;                   // ~66.5 KB
    cudaFuncSetAttribute(k1, cudaFuncAttributeMaxDynamicSharedMemorySize, smem1);
    cudaFuncSetAttribute(k3, cudaFuncAttributeMaxDynamicSharedMemorySize, smem3);

    k1<<<(Bq * Vq) / 256, 576, smem1>>>(X, W1, b1, W2, b2, Wout);

    kB2<<<Bq, 576>>>(Wout);

    k3<<<(Bq * Vq) / 256, 512, smem3>>>(bout, out);
}